// round 7
// baseline (speedup 1.0000x reference)
#include <cuda_runtime.h>
#include <cuda_bf16.h>

// Gridding R5: parity-grid scratch (2 v4 REDs/point) + batch phasing so the
// 32MB scratch stays L2-resident. Remap zero-writes scratch slots after
// reading, replacing inter-phase memsets.

#define GRID_S    32
#define GRID_G    64
#define NPTS_LOG2 18
#define NBATCH    32
#define NB_PHASE  8            // batches per phase
#define NPHASE    (NBATCH / NB_PHASE)

// 4 grids x 8 batches x 2^18 floats = 32 MB scratch (reused across phases)
__device__ float g_scratch[4][NB_PHASE][1 << NPTS_LOG2];

__device__ __forceinline__ void red_v4(float* p, float a, float b, float c, float d) {
    asm volatile("red.global.add.v4.f32 [%0], {%1, %2, %3, %4};"
                 :: "l"(p), "f"(a), "f"(b), "f"(c), "f"(d) : "memory");
}

__global__ __launch_bounds__(256)
void gridding_scatter_kernel(const float* __restrict__ pt, int npts_phase)
{
    int i = blockIdx.x * blockDim.x + threadIdx.x;
    if (i >= npts_phase) return;

    float x = pt[3 * i + 0] * (float)GRID_S;
    float y = pt[3 * i + 1] * (float)GRID_S;
    float z = pt[3 * i + 2] * (float)GRID_S;

    // drop points whose scaled coord-sum is exactly 0 (x32 scaling is exact)
    float m = ((x + y + z) != 0.0f) ? 1.0f : 0.0f;

    float fx = floorf(x), fy = floorf(y), fz = floorf(z);
    float dx = x - fx, dy = y - fy, dz = z - fz;

    int ix = min(max(__float2int_rn(fx) + GRID_S, 0), GRID_G - 2);
    int iy = min(max(__float2int_rn(fy) + GRID_S, 0), GRID_G - 2);
    int iz = min(max(__float2int_rn(fz) + GRID_S, 0), GRID_G - 2);

    float wx0 = (1.0f - dx) * m;
    float wx1 = dx * m;
    float wy0 = 1.0f - dy, wy1 = dy;
    float wz0 = 1.0f - dz, wz1 = dz;

    int b   = i >> NPTS_LOG2;           // batch-local within phase, [0,8)
    int phi = iy & 1;
    int zb  = iz & 1;
    int p   = iy >> 1;

    int gidx = phi * 2 + zb;
    int pos = (ix << 12) + (p << 7) + 2 * (iz & ~1);   // 16B aligned
    float* base = &g_scratch[gidx][b][pos];

    float a0 = wy0 * wz0, a1 = wy1 * wz0, a2 = wy0 * wz1, a3 = wy1 * wz1;
    red_v4(base,        wx0 * a0, wx0 * a1, wx0 * a2, wx0 * a3);
    red_v4(base + 4096, wx1 * a0, wx1 * a1, wx1 * a2, wx1 * a3);
}

__global__ __launch_bounds__(256)
void gridding_remap_kernel(float* __restrict__ out, int total)
{
    int idx = blockIdx.x * blockDim.x + threadIdx.x;
    if (idx >= total) return;

    int b = idx >> NPTS_LOG2;           // batch-local within phase
    int v = idx & ((1 << NPTS_LOG2) - 1);
    int z = v & 63;
    int y = (v >> 6) & 63;
    int x = v >> 12;

    float acc = 0.0f;

    // phase 0 pairing (iy even): always valid
    {
        int v0 = (x << 12) + ((y >> 1) << 7) + 2 * z + (y & 1);
        float* s0 = &g_scratch[0][b][v0];
        acc += *s0;  *s0 = 0.0f;
        if (v0 >= 2) {
            float* s1 = &g_scratch[1][b][v0 - 2];
            acc += *s1;  *s1 = 0.0f;
        }
    }
    // phase 1 pairing (iy odd): valid for 1 <= y <= 62
    if (y >= 1 && y <= 62) {
        int ym = y - 1;
        int v1 = (x << 12) + ((ym >> 1) << 7) + 2 * z + (ym & 1);
        float* s2 = &g_scratch[2][b][v1];
        acc += *s2;  *s2 = 0.0f;
        if (v1 >= 2) {
            float* s3 = &g_scratch[3][b][v1 - 2];
            acc += *s3;  *s3 = 0.0f;
        }
    }

    out[idx] = acc;
}

extern "C" void kernel_launch(void* const* d_in, const int* in_sizes, int n_in,
                              void* d_out, int out_size)
{
    const float* ptcloud = (const float*)d_in[0];
    float* out = (float*)d_out;

    int total_pts = in_sizes[0] / 3;            // 32 * 262144
    int pts_phase = total_pts / NPHASE;         // 8 * 262144
    int out_phase = out_size / NPHASE;          // 8 * 262144

    // First-ever-run init; later replays find scratch already re-zeroed by
    // remap's zero-writes, memset is then a cheap idempotent L2 write.
    void* scratch_ptr = nullptr;
    cudaGetSymbolAddress(&scratch_ptr, g_scratch);
    cudaMemsetAsync(scratch_ptr, 0, sizeof(g_scratch), 0);

    const int threads = 256;
    int sblocks = (pts_phase + threads - 1) / threads;
    int rblocks = (out_phase + threads - 1) / threads;

    for (int ph = 0; ph < NPHASE; ph++) {
        gridding_scatter_kernel<<<sblocks, threads>>>(
            ptcloud + (size_t)ph * pts_phase * 3, pts_phase);
        gridding_remap_kernel<<<rblocks, threads>>>(
            out + (size_t)ph * out_phase, out_phase);
    }
}

// round 8
// speedup vs baseline: 4.2655x; 4.2655x over previous
#include <cuda_runtime.h>
#include <cuda_bf16.h>

// Gridding R7: parity-grid scratch (2 v4 REDs/point), 2 phases x 16 batches so
// the 64MB scratch stays L2-resident. Explicit memset per phase; remap is the
// R4 pure-read form (no fused zero-stores -- R5 showed those serialize).

#define GRID_S    32
#define GRID_G    64
#define NPTS_LOG2 18
#define NBATCH    32
#define NB_PHASE  16
#define NPHASE    (NBATCH / NB_PHASE)

// 4 grids x 16 batches x 2^18 floats = 64 MB scratch (reused across phases)
__device__ float g_scratch[4][NB_PHASE][1 << NPTS_LOG2];

__device__ __forceinline__ void red_v4(float* p, float a, float b, float c, float d) {
    asm volatile("red.global.add.v4.f32 [%0], {%1, %2, %3, %4};"
                 :: "l"(p), "f"(a), "f"(b), "f"(c), "f"(d) : "memory");
}

__global__ __launch_bounds__(256)
void gridding_scatter_kernel(const float* __restrict__ pt, int npts_phase)
{
    int i = blockIdx.x * blockDim.x + threadIdx.x;
    if (i >= npts_phase) return;

    // evict-first: points are read once; keep L2 for the scratch grids
    float x = __ldcs(&pt[3 * i + 0]) * (float)GRID_S;
    float y = __ldcs(&pt[3 * i + 1]) * (float)GRID_S;
    float z = __ldcs(&pt[3 * i + 2]) * (float)GRID_S;

    // drop points whose scaled coord-sum is exactly 0 (x32 scaling is exact)
    float m = ((x + y + z) != 0.0f) ? 1.0f : 0.0f;

    float fx = floorf(x), fy = floorf(y), fz = floorf(z);
    float dx = x - fx, dy = y - fy, dz = z - fz;   // fractions from UNCLIPPED floor

    int ix = min(max(__float2int_rn(fx) + GRID_S, 0), GRID_G - 2);
    int iy = min(max(__float2int_rn(fy) + GRID_S, 0), GRID_G - 2);
    int iz = min(max(__float2int_rn(fz) + GRID_S, 0), GRID_G - 2);

    float wx0 = (1.0f - dx) * m;
    float wx1 = dx * m;
    float wy0 = 1.0f - dy, wy1 = dy;
    float wz0 = 1.0f - dz, wz1 = dz;

    int b   = i >> NPTS_LOG2;           // batch-local within phase, [0,16)
    int phi = iy & 1;
    int zb  = iz & 1;
    int p   = iy >> 1;

    int gidx = phi * 2 + zb;
    int pos = (ix << 12) + (p << 7) + 2 * (iz & ~1);   // 16B aligned
    float* base = &g_scratch[gidx][b][pos];

    // lanes: {(y0,z0), (y1,z0), (y0,z1), (y1,z1)}
    float a0 = wy0 * wz0, a1 = wy1 * wz0, a2 = wy0 * wz1, a3 = wy1 * wz1;
    red_v4(base,        wx0 * a0, wx0 * a1, wx0 * a2, wx0 * a3);
    red_v4(base + 4096, wx1 * a0, wx1 * a1, wx1 * a2, wx1 * a3);   // x+1: +32*128
}

__global__ __launch_bounds__(256)
void gridding_remap_kernel(float* __restrict__ out, int total)
{
    int idx = blockIdx.x * blockDim.x + threadIdx.x;
    if (idx >= total) return;

    int b = idx >> NPTS_LOG2;           // batch-local within phase
    int v = idx & ((1 << NPTS_LOG2) - 1);
    int z = v & 63;
    int y = (v >> 6) & 63;
    int x = v >> 12;

    float acc = 0.0f;

    // phase-0 pairing (iy even): always valid
    {
        int v0 = (x << 12) + ((y >> 1) << 7) + 2 * z + (y & 1);
        acc += g_scratch[0][b][v0];
        if (v0 >= 2) acc += g_scratch[1][b][v0 - 2];
    }
    // phase-1 pairing (iy odd): valid for 1 <= y <= 62
    if (y >= 1 && y <= 62) {
        int ym = y - 1;
        int v1 = (x << 12) + ((ym >> 1) << 7) + 2 * z + (ym & 1);
        acc += g_scratch[2][b][v1];
        if (v1 >= 2) acc += g_scratch[3][b][v1 - 2];
    }

    out[idx] = acc;
}

extern "C" void kernel_launch(void* const* d_in, const int* in_sizes, int n_in,
                              void* d_out, int out_size)
{
    const float* ptcloud = (const float*)d_in[0];
    float* out = (float*)d_out;

    int total_pts = in_sizes[0] / 3;            // 32 * 262144
    int pts_phase = total_pts / NPHASE;         // 16 * 262144
    int out_phase = out_size / NPHASE;          // 16 * 262144

    void* scratch_ptr = nullptr;
    cudaGetSymbolAddress(&scratch_ptr, g_scratch);

    const int threads = 256;
    int sblocks = (pts_phase + threads - 1) / threads;
    int rblocks = (out_phase + threads - 1) / threads;

    for (int ph = 0; ph < NPHASE; ph++) {
        cudaMemsetAsync(scratch_ptr, 0, sizeof(g_scratch), 0);
        gridding_scatter_kernel<<<sblocks, threads>>>(
            ptcloud + (size_t)ph * pts_phase * 3, pts_phase);
        gridding_remap_kernel<<<rblocks, threads>>>(
            out + (size_t)ph * out_phase, out_phase);
    }
}